// round 8
// baseline (speedup 1.0000x reference)
#include <cuda_runtime.h>
#include <cuda_bf16.h>
#include <math.h>

// Problem constants
#define BB 2
#define NN 8192
#define EE 768
#define HH 12
#define DD 64
#define MTOT (BB*NN)        // 16384

// Scratch (device globals: allocation-guard safe)
__device__ float g_Q[BB*NN*EE];
__device__ float g_K[BB*NN*EE];
__device__ float g_V[BB*NN*EE];
__device__ float g_O4[BB*NN*EE];
__device__ float g_part[32*BB*EE];
__device__ float g_inv[BB*EE];

// ---------------------------------------------------------------------------
// Zero the attention scatter buffer
// ---------------------------------------------------------------------------
__global__ void zero_O4_kernel() {
    size_t i = (size_t)blockIdx.x * blockDim.x + threadIdx.x;
    ((float4*)g_O4)[i] = make_float4(0.f, 0.f, 0.f, 0.f);
}

// ---------------------------------------------------------------------------
// bf16x6 tensor-core GEMM with RZ-bias-free accumulation:
//  - exact 3-way bf16 split (a+b+c = fp32 x), products aa,ab,ba,ac,ca,bb
//  - MMA chains restarted every K-block (zero C-operand), spilled to a
//    master fp32 accumulator with RN adds -> accumulation error ~ fp32 level
// C[m,n] = alpha * ( sum_k A[m,k]*(colscale? cs[b(m),k]:1) * W[n,k] + bias[n] )
// M=16384, N=K=768. CTA 128x128, K-block 32, 8 warps (4Mx2N), warp tile 32x64.
// ---------------------------------------------------------------------------
#define BLDA 40                    // smem row stride in bf16 (80B)
#define SPL  (128*BLDA)            // ushorts per split buffer
#define SPLB (SPL*2u)              // bytes per split buffer (10240)
#define GEMM_SMEM_BYTES (6*SPLB)   // 61440

__device__ __forceinline__ unsigned short bfr(float x) {
    __nv_bfloat16 h = __float2bfloat16_rn(x);
    return *(unsigned short*)&h;
}
__device__ __forceinline__ float bff(unsigned short u) {
    __nv_bfloat16 h = *(__nv_bfloat16*)&u;
    return __bfloat162float(h);
}
__device__ __forceinline__ void split3(float x, unsigned short &a, unsigned short &b, unsigned short &c) {
    a = bfr(x);          float r1 = x - bff(a);
    b = bfr(r1);         float r2 = r1 - bff(b);
    c = bfr(r2);
}

// chained: d += a*b (C = D)
__device__ __forceinline__ void mma_bf16(float* acc, const unsigned* a, unsigned b0, unsigned b1) {
    asm volatile(
        "mma.sync.aligned.m16n8k16.row.col.f32.bf16.bf16.f32 "
        "{%0,%1,%2,%3}, {%4,%5,%6,%7}, {%8,%9}, {%0,%1,%2,%3};"
        : "+f"(acc[0]), "+f"(acc[1]), "+f"(acc[2]), "+f"(acc[3])
        : "r"(a[0]), "r"(a[1]), "r"(a[2]), "r"(a[3]), "r"(b0), "r"(b1));
}
// chain restart: d = a*b + 0 (C = zeros, D fresh)
__device__ __forceinline__ void mma_bf16_z(float* d, const unsigned* a, unsigned b0, unsigned b1) {
    asm volatile(
        "mma.sync.aligned.m16n8k16.row.col.f32.bf16.bf16.f32 "
        "{%0,%1,%2,%3}, {%4,%5,%6,%7}, {%8,%9}, {%10,%11,%12,%13};"
        : "=f"(d[0]), "=f"(d[1]), "=f"(d[2]), "=f"(d[3])
        : "r"(a[0]), "r"(a[1]), "r"(a[2]), "r"(a[3]), "r"(b0), "r"(b1),
          "f"(0.f), "f"(0.f), "f"(0.f), "f"(0.f));
}
__device__ __forceinline__ void ldsm4(unsigned* d, unsigned addr) {
    asm volatile("ldmatrix.sync.aligned.m8n8.x4.shared.b16 {%0,%1,%2,%3}, [%4];"
                 : "=r"(d[0]), "=r"(d[1]), "=r"(d[2]), "=r"(d[3]) : "r"(addr));
}

__global__ __launch_bounds__(256) void gemm768_tc_kernel(
    const float* __restrict__ A, const float* __restrict__ W,
    const float* __restrict__ bias, const float* __restrict__ colscale,
    float alpha, float* __restrict__ C)
{
    extern __shared__ unsigned short smu[];
    unsigned short* AsA = smu;            // A splits a,b,c then B splits a,b,c
    unsigned short* BsA = smu + 3*SPL;

    const int tid  = threadIdx.x;
    const int lane = tid & 31;
    const int wid  = tid >> 5;
    const int warp_m = wid & 3;    // 4 warps along M (32 each)
    const int warp_n = wid >> 2;   // 2 warps along N (64 each)
    const int m0 = blockIdx.y * 128;
    const int n0 = blockIdx.x * 128;

    const int lcol = tid & 7;      // float4 index along k (32 wide)
    const int lrow = tid >> 3;     // 0..31, +32 per pass

    float acc[2][8][4];            // master accumulator (RN adds only)
    float accm[2][8][4];           // per-K-block MMA chain accumulator
#pragma unroll
    for (int mt = 0; mt < 2; ++mt)
#pragma unroll
        for (int nt = 0; nt < 8; ++nt)
#pragma unroll
            for (int r = 0; r < 4; ++r) acc[mt][nt][r] = 0.f;

    // ldmatrix base addresses. Rows are 80B; lanes 0-15 address the 16 rows of a
    // 16-row group at +0B, lanes 16-31 the same rows at +16B (second k-half).
    const unsigned a_base = (unsigned)__cvta_generic_to_shared(
        AsA + (warp_m*32 + (lane & 15))*BLDA) + ((lane >> 4) << 4);
    const unsigned b_base = (unsigned)__cvta_generic_to_shared(
        BsA + (warp_n*64 + (lane & 15))*BLDA) + ((lane >> 4) << 4);

    for (int kb = 0; kb < 768; kb += 32) {
#pragma unroll
        for (int l = 0; l < 4; ++l) {
            int r = lrow + l*32;
            float4 av = *(const float4*)(A + (size_t)(m0 + r)*768 + kb + lcol*4);
            if (colscale) {
                float4 cs = *(const float4*)(colscale + ((m0 + r) >> 13)*768 + kb + lcol*4);
                av.x *= cs.x; av.y *= cs.y; av.z *= cs.z; av.w *= cs.w;
            }
            ushort4 sa, sb, sc;
            split3(av.x, sa.x, sb.x, sc.x); split3(av.y, sa.y, sb.y, sc.y);
            split3(av.z, sa.z, sb.z, sc.z); split3(av.w, sa.w, sb.w, sc.w);
            int off = r*BLDA + lcol*4;
            *(ushort4*)(AsA + off)         = sa;
            *(ushort4*)(AsA + SPL + off)   = sb;
            *(ushort4*)(AsA + 2*SPL + off) = sc;

            float4 wv = *(const float4*)(W + (size_t)(n0 + r)*768 + kb + lcol*4);
            split3(wv.x, sa.x, sb.x, sc.x); split3(wv.y, sa.y, sb.y, sc.y);
            split3(wv.z, sa.z, sb.z, sc.z); split3(wv.w, sa.w, sc.w = sc.w, sc.w), // (no-op guard)
            split3(wv.z, sa.z, sb.z, sc.z); split3(wv.w, sa.w, sb.w, sc.w);
            split3(wv.x, sa.x, sb.x, sc.x); split3(wv.y, sa.y, sb.y, sc.y);
            *(ushort4*)(BsA + off)         = sa;
            *(ushort4*)(BsA + SPL + off)   = sb;
            *(ushort4*)(BsA + 2*SPL + off) = sc;
        }
        __syncthreads();

#pragma unroll
        for (int ks = 0; ks < 2; ++ks) {
            // A fragments: [mt][split][4]
            unsigned af[2][3][4];
#pragma unroll
            for (int mt = 0; mt < 2; ++mt)
#pragma unroll
                for (int s = 0; s < 3; ++s)
                    ldsm4(af[mt][s], a_base + s*SPLB + mt*(16*80) + ks*32);

#pragma unroll
            for (int p = 0; p < 4; ++p) {      // 4 pairs of n-tiles (16 rows each)
                unsigned bf[3][4];
#pragma unroll
                for (int s = 0; s < 3; ++s)
                    ldsm4(bf[s], b_base + s*SPLB + p*(16*80) + ks*32);
#pragma unroll
                for (int mt = 0; mt < 2; ++mt)
#pragma unroll
                    for (int h = 0; h < 2; ++h) {
                        float* ac = accm[mt][p*2 + h];
                        if (ks == 0)
                            mma_bf16_z(ac, af[mt][1], bf[1][h], bf[1][h+2]); // b*b (chain restart)
                        else
                            mma_bf16(ac, af[mt][1], bf[1][h], bf[1][h+2]);   // b*b
                        mma_bf16(ac, af[mt][2], bf[0][h], bf[0][h+2]);  // c*a
                        mma_bf16(ac, af[mt][0], bf[2][h], bf[2][h+2]);  // a*c
                        mma_bf16(ac, af[mt][1], bf[0][h], bf[0][h+2]);  // b*a
                        mma_bf16(ac, af[mt][0], bf[1][h], bf[1][h+2]);  // a*b
                        mma_bf16(ac, af[mt][0], bf[0][h], bf[0][h+2]);  // a*a
                    }
            }
        }
        // spill chain accumulators into master with RN adds
#pragma unroll
        for (int mt = 0; mt < 2; ++mt)
#pragma unroll
            for (int nt = 0; nt < 8; ++nt)
#pragma unroll
                for (int r = 0; r < 4; ++r)
                    acc[mt][nt][r] += accm[mt][nt][r];
        __syncthreads();
    }

    // Epilogue: (acc + bias) * alpha, coalesced float2 stores
    const int r0 = lane >> 2;
    const int c0 = (lane & 3) * 2;
#pragma unroll
    for (int mt = 0; mt < 2; ++mt) {
#pragma unroll
        for (int nt = 0; nt < 8; ++nt) {
            int col = n0 + warp_n*64 + nt*8 + c0;
            float b0 = bias[col], b1 = bias[col + 1];
            int row_t = m0 + warp_m*32 + mt*16 + r0;
            float2 v0, v1;
            v0.x = (acc[mt][nt][0] + b0)*alpha; v0.y = (acc[mt][nt][1] + b1)*alpha;
            v1.x = (acc[mt][nt][2] + b0)*alpha; v1.y = (acc[mt][nt][3] + b1)*alpha;
            *(float2*)(C + (size_t)row_t*768 + col)       = v0;
            *(float2*)(C + (size_t)(row_t + 8)*768 + col) = v1;
        }
    }
}

// ---------------------------------------------------------------------------
// Dilated flash attention (scalar fp32 — best verified version).
// grid: x = q-tile (16 tiles of 128 over L=2048), y = instance (56 total)
// ---------------------------------------------------------------------------
#define ATTN_SMEM_FLOATS (64*132 + 64*68 + 64*64 + 64*132)
#define ATTN_SMEM_BYTES  (ATTN_SMEM_FLOATS*4)

__global__ __launch_bounds__(256, 2) void attn_kernel()
{
    extern __shared__ float sm[];
    float* Qst = sm;                      // [d=64][m=128] ld 132
    float* Kst = sm + 64*132;             // [d=64][n=64]  ld 68
    float* Vs  = Kst + 64*68;             // [k=64][d=64]  ld 64
    float* Pst = Vs + 64*64;              // [k=64][m=128] ld 132

    const int tid = threadIdx.x;
    const int tx = tid & 15, ty = tid >> 4;

    const int inst = blockIdx.y;
    int grp, b, seg, hl;
    if (inst < 32)      { grp = 0; b = inst >> 4;        seg = (inst >> 2) & 3; hl = inst & 3; }
    else if (inst < 48) { int r = inst - 32; grp = 1; b = r >> 3; seg = (r >> 2) & 1; hl = r & 3; }
    else                { int r = inst - 48; grp = 2; b = r >> 2; seg = 0;            hl = r & 3; }
    const int rate = 1 << grp;
    const int slen = 2048 << grp;
    const int off  = grp;
    const int head = grp*4 + hl;
    const int q0   = blockIdx.x * 128;

    const size_t base = (size_t)b*NN*EE + (size_t)(seg*slen + off)*EE + head*DD;
    const int stride = rate * EE;

#pragma unroll
    for (int l = 0; l < 8; ++l) {
        int idx = tid + l*256;
        int row = idx >> 4;
        int c4  = idx & 15;
        float4 v = *(const float4*)(g_Q + base + (size_t)(q0 + row)*stride + c4*4);
        Qst[(c4*4+0)*132 + row] = v.x;
        Qst[(c4*4+1)*132 + row] = v.y;
        Qst[(c4*4+2)*132 + row] = v.z;
        Qst[(c4*4+3)*132 + row] = v.w;
    }

    float m_i[8], l_i[8], O[8][4];
#pragma unroll
    for (int i = 0; i < 8; ++i) {
        m_i[i] = -1e30f; l_i[i] = 0.f;
#pragma unroll
        for (int j = 0; j < 4; ++j) O[i][j] = 0.f;
    }

    for (int kt = 0; kt < 32; ++kt) {
        const int k0 = kt * 64;
        __syncthreads();
#pragma unroll
        for (int l = 0; l < 4; ++l) {
            int idx = tid + l*256;
            int row = idx >> 4;
            int c4  = idx & 15;
            float4 kv = *(const float4*)(g_K + base + (size_t)(k0 + row)*stride + c4*4);
            Kst[(c4*4+0)*68 + row] = kv.x;
            Kst[(c4*4+1)*68 + row] = kv.y;
            Kst[(c4*4+2)*68 + row] = kv.z;
            Kst[(c4*4+3)*68 + row] = kv.w;
            float4 vv = *(const float4*)(g_V + base + (size_t)(k0 + row)*stride + c4*4);
            *(float4*)(Vs + row*64 + c4*4) = vv;
        }
        __syncthreads();

        float S[8][4];
#pragma unroll
        for (int i = 0; i < 8; ++i)
#pragma unroll
            for (int j = 0; j < 4; ++j) S[i][j] = 0.f;
#pragma unroll 8
        for (int k = 0; k < 64; ++k) {
            float4 a0 = *(const float4*)(Qst + k*132 + ty*8);
            float4 a1 = *(const float4*)(Qst + k*132 + ty*8 + 4);
            float4 bv = *(const float4*)(Kst + k*68 + tx*4);
            float a[8] = {a0.x,a0.y,a0.z,a0.w,a1.x,a1.y,a1.z,a1.w};
#pragma unroll
            for (int i = 0; i < 8; ++i) {
                S[i][0] += a[i]*bv.x;
                S[i][1] += a[i]*bv.y;
                S[i][2] += a[i]*bv.z;
                S[i][3] += a[i]*bv.w;
            }
        }

#pragma unroll
        for (int i = 0; i < 8; ++i) {
            float mx = fmaxf(fmaxf(S[i][0], S[i][1]), fmaxf(S[i][2], S[i][3]));
#pragma unroll
            for (int w = 8; w > 0; w >>= 1)
                mx = fmaxf(mx, __shfl_xor_sync(0xffffffffu, mx, w));
            float mnew = fmaxf(m_i[i], mx);
            float corr = __expf(m_i[i] - mnew);
            m_i[i] = mnew;
            float rs = 0.f;
#pragma unroll
            for (int j = 0; j < 4; ++j) {
                float p = __expf(S[i][j] - mnew);
                S[i][j] = p;
                rs += p;
            }
#pragma unroll
            for (int w = 8; w > 0; w >>= 1)
                rs += __shfl_xor_sync(0xffffffffu, rs, w);
            l_i[i] = l_i[i]*corr + rs;
#pragma unroll
            for (int j = 0; j < 4; ++j) {
                O[i][j] *= corr;
                Pst[(tx*4+j)*132 + ty*8 + i] = S[i][j];
            }
        }
        __syncthreads();

#pragma unroll 8
        for (int k = 0; k < 64; ++k) {
            float4 p0 = *(const float4*)(Pst + k*132 + ty*8);
            float4 p1 = *(const float4*)(Pst + k*132 + ty*8 + 4);
            float4 vv = *(const float4*)(Vs + k*64 + tx*4);
            float p[8] = {p0.x,p0.y,p0.z,p0.w,p1.x,p1.y,p1.z,p1.w};
#pragma unroll
            for (int i = 0; i < 8; ++i) {
                O[i][0] += p[i]*vv.x;
                O[i][1] += p[i]*vv.y;
                O[i][2] += p[i]*vv.z;
                O[i][3] += p[i]*vv.w;
            }
        }
    }

#pragma unroll
    for (int i = 0; i < 8; ++i) {
        float inv = 1.0f / l_i[i];
        float4 o;
        o.x = O[i][0]*inv; o.y = O[i][1]*inv; o.z = O[i][2]*inv; o.w = O[i][3]*inv;
        int p = q0 + ty*8 + i;
        *(float4*)(g_O4 + base + (size_t)p*stride + tx*4) = o;
    }
}

// ---------------------------------------------------------------------------
// denom[b,c] = sum_n O4[b,n,c]; two-phase deterministic reduction
// ---------------------------------------------------------------------------
__global__ void colsum_part_kernel()
{
    int chunk = blockIdx.x;
    int bc    = blockIdx.y;
    int b  = bc / 3;
    int c  = (bc % 3)*256 + threadIdx.x;
    const float* p = g_O4 + ((size_t)b*NN + chunk*256)*EE + c;
    float s = 0.f;
#pragma unroll 8
    for (int n = 0; n < 256; ++n) {
        s += *p;
        p += EE;
    }
    g_part[chunk*(BB*EE) + b*EE + c] = s;
}

__global__ void colsum_reduce_kernel()
{
    int i = blockIdx.x*256 + threadIdx.x;
    float s = 0.f;
#pragma unroll
    for (int ch = 0; ch < 32; ++ch) s += g_part[ch*(BB*EE) + i];
    g_inv[i] = 1.0f / s;
}

// ---------------------------------------------------------------------------
extern "C" void kernel_launch(void* const* d_in, const int* in_sizes, int n_in,
                              void* d_out, int out_size)
{
    const float* query = (const float*)d_in[0];
    const float* key   = (const float*)d_in[1];
    const float* value = (const float*)d_in[2];
    const float* Wq = (const float*)d_in[3];
    const float* bq = (const float*)d_in[4];
    const float* Wk = (const float*)d_in[5];
    const float* bk = (const float*)d_in[6];
    const float* Wv = (const float*)d_in[7];
    const float* bv = (const float*)d_in[8];
    const float* Wo = (const float*)d_in[9];
    const float* bo = (const float*)d_in[10];
    float* out = (float*)d_out;

    float *pQ, *pK, *pV, *pO4, *pInv;
    cudaGetSymbolAddress((void**)&pQ,   g_Q);
    cudaGetSymbolAddress((void**)&pK,   g_K);
    cudaGetSymbolAddress((void**)&pV,   g_V);
    cudaGetSymbolAddress((void**)&pO4,  g_O4);
    cudaGetSymbolAddress((void**)&pInv, g_inv);

    cudaFuncSetAttribute(attn_kernel,
                         cudaFuncAttributeMaxDynamicSharedMemorySize,
                         ATTN_SMEM_BYTES);
    cudaFuncSetAttribute(gemm768_tc_kernel,
                         cudaFuncAttributeMaxDynamicSharedMemorySize,
                         GEMM_SMEM_BYTES);

    // 1. zero scatter buffer
    zero_O4_kernel<<<12288, 256>>>();

    // 2. projections on tensor cores, bf16x6 + RN respill (Q pre-scaled 1/8)
    dim3 gg(6, 128);
    gemm768_tc_kernel<<<gg, 256, GEMM_SMEM_BYTES>>>(query, Wq, bq, nullptr, 0.125f, pQ);
    gemm768_tc_kernel<<<gg, 256, GEMM_SMEM_BYTES>>>(key,   Wk, bk, nullptr, 1.0f,   pK);
    gemm768_tc_kernel<<<gg, 256, GEMM_SMEM_BYTES>>>(value, Wv, bv, nullptr, 1.0f,   pV);

    // 3. dilated attention (56 instances x 16 q-tiles)
    attn_kernel<<<dim3(16, 56), 256, ATTN_SMEM_BYTES>>>();

    // 4. sequence-sum normalization factors
    colsum_part_kernel<<<dim3(32, 6), 256>>>();
    colsum_reduce_kernel<<<6, 256>>>();

    // 5. output projection with fused per-(b,col) 1/denom scaling
    gemm768_tc_kernel<<<gg, 256, GEMM_SMEM_BYTES>>>(pO4, Wo, bo, pInv, 1.0f, out);
}